// round 11
// baseline (speedup 1.0000x reference)
#include <cuda_runtime.h>

// Problem constants
#define BATCH 32
#define SEQ   512
#define DIM   64
#define VOCAB 32000
#define DECAY 0.9f

#define T_CHUNK 16
#define NCHUNK  32                      // SEQ / T_CHUNK
#define DC      0.1853020188851841f     // 0.9^16 (chunk decay)
#define MTERMS  8                       // carry terms kept; err ~0.9^128 = 1.4e-6

// Scratch: per-chunk local sums L_k [B][NCHUNK][D][D] = 16 MB (L2-resident)
__device__ float g_L[BATCH * NCHUNK * DIM * DIM];

// W[s] = 0.9^((15-s)/2): pre-scale so L accumulates with pure FFMA.
__device__ __constant__ float c_W[T_CHUNK] = {
    0.45375228053933687f, 0.47829690000000000f, 0.50416920059926320f,
    0.53144100000000000f, 0.56018800066584800f, 0.59049000000000000f,
    0.62243111185094220f, 0.65610000000000000f, 0.69159012427882460f,
    0.72900000000000000f, 0.76843347142091620f, 0.81000000000000000f,
    0.85381496824546250f, 0.90000000000000000f, 0.94868329805051380f,
    1.00000000000000000f
};

// ---------------------------------------------------------------------------
// Kernel B1: gather (pre-scaled) + per-chunk local decayed sums, SYMMETRIC.
// L_k is symmetric: compute only the 136 upper-triangle 4x4 tiles (threads
// 0..135; warps 5-7 idle -> ~53% of the FFMA issue), mirror on store.
// ---------------------------------------------------------------------------
__global__ __launch_bounds__(256)
void qmn_chunk_sum(const int* __restrict__ x, const float* __restrict__ emb) {
    __shared__ __align__(16) float sc[T_CHUNK * DIM];   // 4 KB

    const int b   = blockIdx.x >> 5;   // NCHUNK = 32
    const int k   = blockIdx.x & 31;
    const int tid = threadIdx.x;

    {   // one float4 per thread, scaled by W[s]
        const int s  = tid >> 4;
        const int d4 = tid & 15;
        int tok = x[b * SEQ + k * T_CHUNK + s];
        tok = min(max(tok, 0), VOCAB - 1);
        float4 v = reinterpret_cast<const float4*>(emb + (size_t)tok * DIM)[d4];
        const float w = c_W[s];
        v.x *= w; v.y *= w; v.z *= w; v.w *= w;
        reinterpret_cast<float4*>(sc)[tid] = v;
    }
    __syncthreads();

    if (tid >= 136) return;            // only upper-triangle tiles

    // Triangular decode: tile (r, c), r <= c, from linear index tid.
    // cum(r) = 16r - r(r-1)/2 tiles precede row r.
    int r = (int)((33.0f - sqrtf(1089.0f - 8.0f * (float)tid)) * 0.5f);
    int cum = 16 * r - (r * (r - 1)) / 2;
    while (cum > tid)              { r--; cum = 16 * r - (r * (r - 1)) / 2; }
    while (cum + (16 - r) <= tid)  { cum += 16 - r; r++; }
    const int c  = r + (tid - cum);
    const int i0 = r * 4;
    const int j0 = c * 4;

    float4 L[4];
    #pragma unroll
    for (int rr = 0; rr < 4; rr++) L[rr] = make_float4(0.f, 0.f, 0.f, 0.f);

    #pragma unroll
    for (int t = 0; t < T_CHUNK; t++) {
        const float4 ci = *reinterpret_cast<const float4*>(sc + t * DIM + i0);
        const float4 cj = *reinterpret_cast<const float4*>(sc + t * DIM + j0);
        const float cv[4] = {ci.x, ci.y, ci.z, ci.w};
        #pragma unroll
        for (int rr = 0; rr < 4; rr++) {
            L[rr].x = fmaf(cv[rr], cj.x, L[rr].x);
            L[rr].y = fmaf(cv[rr], cj.y, L[rr].y);
            L[rr].z = fmaf(cv[rr], cj.z, L[rr].z);
            L[rr].w = fmaf(cv[rr], cj.w, L[rr].w);
        }
    }

    float* Lp = g_L + (size_t)blockIdx.x * DIM * DIM;
    #pragma unroll
    for (int rr = 0; rr < 4; rr++)
        __stcg(reinterpret_cast<float4*>(Lp + (i0 + rr) * DIM + j0), L[rr]);

    if (r != c) {                      // mirror: transposed tile at (c, r)
        float4 T[4];
        T[0] = make_float4(L[0].x, L[1].x, L[2].x, L[3].x);
        T[1] = make_float4(L[0].y, L[1].y, L[2].y, L[3].y);
        T[2] = make_float4(L[0].z, L[1].z, L[2].z, L[3].z);
        T[3] = make_float4(L[0].w, L[1].w, L[2].w, L[3].w);
        #pragma unroll
        for (int rr = 0; rr < 4; rr++)
            __stcg(reinterpret_cast<float4*>(Lp + (j0 + rr) * DIM + i0), T[rr]);
    }
}

// ---------------------------------------------------------------------------
// Kernel C: state emission (1024 blocks) — unchanged from R10 (best config).
// ---------------------------------------------------------------------------
__global__ __launch_bounds__(256)
void qmn_states(const int* __restrict__ x, const float* __restrict__ emb,
                float* __restrict__ out) {
    __shared__ __align__(16) float sc[T_CHUNK * DIM];   // 4 KB

    const int b   = blockIdx.x >> 5;
    const int k   = blockIdx.x & 31;
    const int tid = threadIdx.x;

    // ---- Gather this chunk's content (unscaled) — issue loads early ----
    {
        const int s  = tid >> 4;
        const int d4 = tid & 15;
        int tok = x[b * SEQ + k * T_CHUNK + s];
        tok = min(max(tok, 0), VOCAB - 1);
        reinterpret_cast<float4*>(sc)[tid] =
            reinterpret_cast<const float4*>(emb + (size_t)tok * DIM)[d4];
    }

    const int i0 = (tid >> 4) * 4;
    const int j0 = (tid & 15) * 4;

    // ---- Truncated carry: acc = sum_m DC^{k-1-m} L_m (+ DC^k I if k<=MTERMS)
    float4 acc[4];
    #pragma unroll
    for (int r = 0; r < 4; r++) acc[r] = make_float4(0.f, 0.f, 0.f, 0.f);

    const float* Lb = g_L + (size_t)b * NCHUNK * DIM * DIM;
    const int mlo = (k - MTERMS > 0) ? (k - MTERMS) : 0;
    float w = 1.0f;
    for (int m = k - 1; m >= mlo; m--) {
        const float* Lp = Lb + (size_t)m * DIM * DIM;
        #pragma unroll
        for (int r = 0; r < 4; r++) {
            const float4 l = *reinterpret_cast<const float4*>(Lp + (i0 + r) * DIM + j0);
            acc[r].x = fmaf(w, l.x, acc[r].x);
            acc[r].y = fmaf(w, l.y, acc[r].y);
            acc[r].z = fmaf(w, l.z, acc[r].z);
            acc[r].w = fmaf(w, l.w, acc[r].w);
        }
        w *= DC;
    }
    if (k <= MTERMS) {                 // loop ran k times -> w == DC^k
        #pragma unroll
        for (int r = 0; r < 4; r++) {
            const int i = i0 + r;
            if (i == j0 + 0) acc[r].x += w;
            if (i == j0 + 1) acc[r].y += w;
            if (i == j0 + 2) acc[r].z += w;
            if (i == j0 + 3) acc[r].w += w;
        }
    }

    __syncthreads();

    // ---- Emit 16 states, barrier-free, streaming stores ----
    float* op = out + ((size_t)b * SEQ + (size_t)k * T_CHUNK) * DIM * DIM;

    #pragma unroll
    for (int t = 0; t < T_CHUNK; t++) {
        const float4 ci = *reinterpret_cast<const float4*>(sc + t * DIM + i0);
        const float4 cj = *reinterpret_cast<const float4*>(sc + t * DIM + j0);
        const float c[4] = {ci.x, ci.y, ci.z, ci.w};
        #pragma unroll
        for (int r = 0; r < 4; r++) {
            acc[r].x = fmaf(acc[r].x, DECAY, c[r] * cj.x);
            acc[r].y = fmaf(acc[r].y, DECAY, c[r] * cj.y);
            acc[r].z = fmaf(acc[r].z, DECAY, c[r] * cj.z);
            acc[r].w = fmaf(acc[r].w, DECAY, c[r] * cj.w);
        }
        float* ot = op + (size_t)t * DIM * DIM;
        #pragma unroll
        for (int r = 0; r < 4; r++)
            __stcs(reinterpret_cast<float4*>(ot + (i0 + r) * DIM + j0), acc[r]);
    }
}

// ---------------------------------------------------------------------------
// Launch
// ---------------------------------------------------------------------------
extern "C" void kernel_launch(void* const* d_in, const int* in_sizes, int n_in,
                              void* d_out, int out_size) {
    const int*   x   = (const int*)d_in[0];     // [B, S] int32
    const float* emb = (const float*)d_in[1];   // [VOCAB, D] fp32
    float*       out = (float*)d_out;           // [B, S, D, D] fp32

    (void)in_sizes; (void)n_in; (void)out_size;

    qmn_chunk_sum<<<BATCH * NCHUNK, 256>>>(x, emb);
    qmn_states<<<BATCH * NCHUNK, 256>>>(x, emb, out);
}

// round 12
// speedup vs baseline: 1.0060x; 1.0060x over previous
#include <cuda_runtime.h>

// Problem constants
#define BATCH 32
#define SEQ   512
#define DIM   64
#define VOCAB 32000
#define DECAY 0.9f

#define T_CHUNK 16
#define NCHUNK  32                      // SEQ / T_CHUNK
#define DC      0.1853020188851841f     // 0.9^16 (chunk decay)
#define MTERMS  8                       // carry terms kept; err ~0.9^128 = 1.4e-6

// Scratch: per-chunk local sums L_k [B][NCHUNK][D][D] = 16 MB (L2-resident)
__device__ float g_L[BATCH * NCHUNK * DIM * DIM];

// W[s] = 0.9^((15-s)/2): pre-scale so L accumulates with pure FFMA.
__device__ __constant__ float c_W[T_CHUNK] = {
    0.45375228053933687f, 0.47829690000000000f, 0.50416920059926320f,
    0.53144100000000000f, 0.56018800066584800f, 0.59049000000000000f,
    0.62243111185094220f, 0.65610000000000000f, 0.69159012427882460f,
    0.72900000000000000f, 0.76843347142091620f, 0.81000000000000000f,
    0.85381496824546250f, 0.90000000000000000f, 0.94868329805051380f,
    1.00000000000000000f
};

// ---- Packed f32x2 helpers (sm_103a FFMA2 path; PTX-only, see SASS_QUICKREF)
__device__ __forceinline__ unsigned long long pack2(float v) {
    unsigned long long r;
    asm("mov.b64 %0, {%1, %1};" : "=l"(r) : "f"(v));
    return r;
}
__device__ __forceinline__ void fma2(unsigned long long& d,
                                     unsigned long long a,
                                     unsigned long long b) {
    asm("fma.rn.f32x2 %0, %1, %2, %0;" : "+l"(d) : "l"(a), "l"(b));
}
__device__ __forceinline__ void unpack2(unsigned long long v, float& lo, float& hi) {
    asm("mov.b64 {%0, %1}, %2;" : "=f"(lo), "=f"(hi) : "l"(v));
}

// ---------------------------------------------------------------------------
// Kernel B1: gather (pre-scaled) + per-chunk local decayed sums.
//   sc[s] = W[s]*c_s  ->  L_k = sum_s sc[s] sc[s]^T
// Inner loop uses fma.rn.f32x2: 8 FFMA2 + 4 packs + 2 LDS per step
// (vs 16 FFMA + 2 LDS scalar). Bit-identical rounding to fmaf per half.
// ---------------------------------------------------------------------------
__global__ __launch_bounds__(256)
void qmn_chunk_sum(const int* __restrict__ x, const float* __restrict__ emb) {
    __shared__ __align__(16) float sc[T_CHUNK * DIM];   // 4 KB

    const int b   = blockIdx.x >> 5;   // NCHUNK = 32
    const int k   = blockIdx.x & 31;
    const int tid = threadIdx.x;

    {   // one float4 per thread, scaled by W[s]
        const int s  = tid >> 4;
        const int d4 = tid & 15;
        int tok = x[b * SEQ + k * T_CHUNK + s];
        tok = min(max(tok, 0), VOCAB - 1);
        float4 v = reinterpret_cast<const float4*>(emb + (size_t)tok * DIM)[d4];
        const float w = c_W[s];
        v.x *= w; v.y *= w; v.z *= w; v.w *= w;
        reinterpret_cast<float4*>(sc)[tid] = v;
    }
    __syncthreads();

    const int i0 = (tid >> 4) * 4;
    const int j0 = (tid & 15) * 4;

    unsigned long long acc[4][2];      // 4 rows x (2 packed f32x2 cols)
    #pragma unroll
    for (int r = 0; r < 4; r++) { acc[r][0] = 0ULL; acc[r][1] = 0ULL; }

    #pragma unroll
    for (int t = 0; t < T_CHUNK; t++) {
        const float4 ci = *reinterpret_cast<const float4*>(sc + t * DIM + i0);
        const ulonglong2 cj = *reinterpret_cast<const ulonglong2*>(sc + t * DIM + j0);
        const float cv[4] = {ci.x, ci.y, ci.z, ci.w};
        #pragma unroll
        for (int r = 0; r < 4; r++) {
            const unsigned long long cc = pack2(cv[r]);
            fma2(acc[r][0], cc, cj.x);
            fma2(acc[r][1], cc, cj.y);
        }
    }

    float* Lp = g_L + (size_t)blockIdx.x * DIM * DIM;
    #pragma unroll
    for (int r = 0; r < 4; r++) {
        float4 v;
        unpack2(acc[r][0], v.x, v.y);
        unpack2(acc[r][1], v.z, v.w);
        __stcg(reinterpret_cast<float4*>(Lp + (i0 + r) * DIM + j0), v);
    }
}

// ---------------------------------------------------------------------------
// Kernel C: state emission (1024 blocks) — byte-identical to R10 (best).
// ---------------------------------------------------------------------------
__global__ __launch_bounds__(256)
void qmn_states(const int* __restrict__ x, const float* __restrict__ emb,
                float* __restrict__ out) {
    __shared__ __align__(16) float sc[T_CHUNK * DIM];   // 4 KB

    const int b   = blockIdx.x >> 5;
    const int k   = blockIdx.x & 31;
    const int tid = threadIdx.x;

    // ---- Gather this chunk's content (unscaled) — issue loads early ----
    {
        const int s  = tid >> 4;
        const int d4 = tid & 15;
        int tok = x[b * SEQ + k * T_CHUNK + s];
        tok = min(max(tok, 0), VOCAB - 1);
        reinterpret_cast<float4*>(sc)[tid] =
            reinterpret_cast<const float4*>(emb + (size_t)tok * DIM)[d4];
    }

    const int i0 = (tid >> 4) * 4;
    const int j0 = (tid & 15) * 4;

    // ---- Truncated carry: acc = sum_m DC^{k-1-m} L_m (+ DC^k I if k<=MTERMS)
    float4 acc[4];
    #pragma unroll
    for (int r = 0; r < 4; r++) acc[r] = make_float4(0.f, 0.f, 0.f, 0.f);

    const float* Lb = g_L + (size_t)b * NCHUNK * DIM * DIM;
    const int mlo = (k - MTERMS > 0) ? (k - MTERMS) : 0;
    float w = 1.0f;
    for (int m = k - 1; m >= mlo; m--) {
        const float* Lp = Lb + (size_t)m * DIM * DIM;
        #pragma unroll
        for (int r = 0; r < 4; r++) {
            const float4 l = *reinterpret_cast<const float4*>(Lp + (i0 + r) * DIM + j0);
            acc[r].x = fmaf(w, l.x, acc[r].x);
            acc[r].y = fmaf(w, l.y, acc[r].y);
            acc[r].z = fmaf(w, l.z, acc[r].z);
            acc[r].w = fmaf(w, l.w, acc[r].w);
        }
        w *= DC;
    }
    if (k <= MTERMS) {                 // loop ran k times -> w == DC^k
        #pragma unroll
        for (int r = 0; r < 4; r++) {
            const int i = i0 + r;
            if (i == j0 + 0) acc[r].x += w;
            if (i == j0 + 1) acc[r].y += w;
            if (i == j0 + 2) acc[r].z += w;
            if (i == j0 + 3) acc[r].w += w;
        }
    }

    __syncthreads();

    // ---- Emit 16 states, barrier-free, streaming stores ----
    float* op = out + ((size_t)b * SEQ + (size_t)k * T_CHUNK) * DIM * DIM;

    #pragma unroll
    for (int t = 0; t < T_CHUNK; t++) {
        const float4 ci = *reinterpret_cast<const float4*>(sc + t * DIM + i0);
        const float4 cj = *reinterpret_cast<const float4*>(sc + t * DIM + j0);
        const float c[4] = {ci.x, ci.y, ci.z, ci.w};
        #pragma unroll
        for (int r = 0; r < 4; r++) {
            acc[r].x = fmaf(acc[r].x, DECAY, c[r] * cj.x);
            acc[r].y = fmaf(acc[r].y, DECAY, c[r] * cj.y);
            acc[r].z = fmaf(acc[r].z, DECAY, c[r] * cj.z);
            acc[r].w = fmaf(acc[r].w, DECAY, c[r] * cj.w);
        }
        float* ot = op + (size_t)t * DIM * DIM;
        #pragma unroll
        for (int r = 0; r < 4; r++)
            __stcs(reinterpret_cast<float4*>(ot + (i0 + r) * DIM + j0), acc[r]);
    }
}

// ---------------------------------------------------------------------------
// Launch
// ---------------------------------------------------------------------------
extern "C" void kernel_launch(void* const* d_in, const int* in_sizes, int n_in,
                              void* d_out, int out_size) {
    const int*   x   = (const int*)d_in[0];     // [B, S] int32
    const float* emb = (const float*)d_in[1];   // [VOCAB, D] fp32
    float*       out = (float*)d_out;           // [B, S, D, D] fp32

    (void)in_sizes; (void)n_in; (void)out_size;

    qmn_chunk_sum<<<BATCH * NCHUNK, 256>>>(x, emb);
    qmn_states<<<BATCH * NCHUNK, 256>>>(x, emb, out);
}

// round 13
// speedup vs baseline: 1.0322x; 1.0260x over previous
#include <cuda_runtime.h>

// Problem constants
#define BATCH 32
#define SEQ   512
#define DIM   64
#define VOCAB 32000
#define DECAY 0.9f

#define T_CHUNK 16
#define NCHUNK  32                      // SEQ / T_CHUNK
#define DC      0.1853020188851841f     // 0.9^16 (chunk decay)
#define MTERMS  8                       // carry terms kept; err ~0.9^128 = 1.4e-6

// Scratch: per-chunk local sums L_k [B][NCHUNK][D][D] = 16 MB (L2-resident)
__device__ float g_L[BATCH * NCHUNK * DIM * DIM];

// W[s] = 0.9^((15-s)/2): pre-scale so L accumulates with pure FFMA.
__device__ __constant__ float c_W[T_CHUNK] = {
    0.45375228053933687f, 0.47829690000000000f, 0.50416920059926320f,
    0.53144100000000000f, 0.56018800066584800f, 0.59049000000000000f,
    0.62243111185094220f, 0.65610000000000000f, 0.69159012427882460f,
    0.72900000000000000f, 0.76843347142091620f, 0.81000000000000000f,
    0.85381496824546250f, 0.90000000000000000f, 0.94868329805051380f,
    1.00000000000000000f
};

// ---------------------------------------------------------------------------
// Kernel B1: gather (pre-scaled) + per-chunk local decayed sums.
//   sc[s] = W[s] * c_s  ->  L_k = sum_s sc[s] sc[s]^T
// R10 scalar form (proven best; FFMA2 was neutral — B1 is latency-bound).
// ---------------------------------------------------------------------------
__global__ __launch_bounds__(256)
void qmn_chunk_sum(const int* __restrict__ x, const float* __restrict__ emb) {
    __shared__ __align__(16) float sc[T_CHUNK * DIM];   // 4 KB

    const int b   = blockIdx.x >> 5;   // NCHUNK = 32
    const int k   = blockIdx.x & 31;
    const int tid = threadIdx.x;

    {   // one float4 per thread, scaled by W[s]
        const int s  = tid >> 4;
        const int d4 = tid & 15;
        int tok = x[b * SEQ + k * T_CHUNK + s];
        tok = min(max(tok, 0), VOCAB - 1);
        float4 v = reinterpret_cast<const float4*>(emb + (size_t)tok * DIM)[d4];
        const float w = c_W[s];
        v.x *= w; v.y *= w; v.z *= w; v.w *= w;
        reinterpret_cast<float4*>(sc)[tid] = v;
    }
    __syncthreads();

    const int i0 = (tid >> 4) * 4;
    const int j0 = (tid & 15) * 4;

    float4 L[4];
    #pragma unroll
    for (int r = 0; r < 4; r++) L[r] = make_float4(0.f, 0.f, 0.f, 0.f);

    #pragma unroll
    for (int t = 0; t < T_CHUNK; t++) {
        const float4 ci = *reinterpret_cast<const float4*>(sc + t * DIM + i0);
        const float4 cj = *reinterpret_cast<const float4*>(sc + t * DIM + j0);
        const float c[4] = {ci.x, ci.y, ci.z, ci.w};
        #pragma unroll
        for (int r = 0; r < 4; r++) {
            L[r].x = fmaf(c[r], cj.x, L[r].x);
            L[r].y = fmaf(c[r], cj.y, L[r].y);
            L[r].z = fmaf(c[r], cj.z, L[r].z);
            L[r].w = fmaf(c[r], cj.w, L[r].w);
        }
    }

    float* Lp = g_L + (size_t)blockIdx.x * DIM * DIM;
    #pragma unroll
    for (int r = 0; r < 4; r++)
        __stcg(reinterpret_cast<float4*>(Lp + (i0 + r) * DIM + j0), L[r]);
}

// ---------------------------------------------------------------------------
// Kernel C: state emission (1024 blocks), launched with PDL so its gather
// prologue overlaps B1's tail. cudaGridDependencySynchronize() gates the
// first g_L read on B1's completion (implicit trigger at B1 kernel end ->
// full memory visibility).
// ---------------------------------------------------------------------------
__global__ __launch_bounds__(256)
void qmn_states(const int* __restrict__ x, const float* __restrict__ emb,
                float* __restrict__ out) {
    __shared__ __align__(16) float sc[T_CHUNK * DIM];   // 4 KB

    const int b   = blockIdx.x >> 5;
    const int k   = blockIdx.x & 31;
    const int tid = threadIdx.x;

    // ---- Gather this chunk's content — independent of B1, overlaps it ----
    {
        const int s  = tid >> 4;
        const int d4 = tid & 15;
        int tok = x[b * SEQ + k * T_CHUNK + s];
        tok = min(max(tok, 0), VOCAB - 1);
        reinterpret_cast<float4*>(sc)[tid] =
            reinterpret_cast<const float4*>(emb + (size_t)tok * DIM)[d4];
    }

    const int i0 = (tid >> 4) * 4;
    const int j0 = (tid & 15) * 4;

    // ---- Wait for B1's grid (and its g_L writes) before the carry reads ----
    cudaGridDependencySynchronize();

    // ---- Truncated carry: acc = sum_m DC^{k-1-m} L_m (+ DC^k I if k<=MTERMS)
    float4 acc[4];
    #pragma unroll
    for (int r = 0; r < 4; r++) acc[r] = make_float4(0.f, 0.f, 0.f, 0.f);

    const float* Lb = g_L + (size_t)b * NCHUNK * DIM * DIM;
    const int mlo = (k - MTERMS > 0) ? (k - MTERMS) : 0;
    float w = 1.0f;
    for (int m = k - 1; m >= mlo; m--) {
        const float* Lp = Lb + (size_t)m * DIM * DIM;
        #pragma unroll
        for (int r = 0; r < 4; r++) {
            const float4 l = *reinterpret_cast<const float4*>(Lp + (i0 + r) * DIM + j0);
            acc[r].x = fmaf(w, l.x, acc[r].x);
            acc[r].y = fmaf(w, l.y, acc[r].y);
            acc[r].z = fmaf(w, l.z, acc[r].z);
            acc[r].w = fmaf(w, l.w, acc[r].w);
        }
        w *= DC;
    }
    if (k <= MTERMS) {                 // loop ran k times -> w == DC^k
        #pragma unroll
        for (int r = 0; r < 4; r++) {
            const int i = i0 + r;
            if (i == j0 + 0) acc[r].x += w;
            if (i == j0 + 1) acc[r].y += w;
            if (i == j0 + 2) acc[r].z += w;
            if (i == j0 + 3) acc[r].w += w;
        }
    }

    __syncthreads();

    // ---- Emit 16 states, barrier-free, streaming stores ----
    float* op = out + ((size_t)b * SEQ + (size_t)k * T_CHUNK) * DIM * DIM;

    #pragma unroll
    for (int t = 0; t < T_CHUNK; t++) {
        const float4 ci = *reinterpret_cast<const float4*>(sc + t * DIM + i0);
        const float4 cj = *reinterpret_cast<const float4*>(sc + t * DIM + j0);
        const float c[4] = {ci.x, ci.y, ci.z, ci.w};
        #pragma unroll
        for (int r = 0; r < 4; r++) {
            acc[r].x = fmaf(acc[r].x, DECAY, c[r] * cj.x);
            acc[r].y = fmaf(acc[r].y, DECAY, c[r] * cj.y);
            acc[r].z = fmaf(acc[r].z, DECAY, c[r] * cj.z);
            acc[r].w = fmaf(acc[r].w, DECAY, c[r] * cj.w);
        }
        float* ot = op + (size_t)t * DIM * DIM;
        #pragma unroll
        for (int r = 0; r < 4; r++)
            __stcs(reinterpret_cast<float4*>(ot + (i0 + r) * DIM + j0), acc[r]);
    }
}

// ---------------------------------------------------------------------------
// Launch: B1 normally, states with Programmatic Dependent Launch so its
// prologue overlaps B1's tail. Both capturable into a CUDA graph.
// ---------------------------------------------------------------------------
extern "C" void kernel_launch(void* const* d_in, const int* in_sizes, int n_in,
                              void* d_out, int out_size) {
    const int*   x   = (const int*)d_in[0];     // [B, S] int32
    const float* emb = (const float*)d_in[1];   // [VOCAB, D] fp32
    float*       out = (float*)d_out;           // [B, S, D, D] fp32

    (void)in_sizes; (void)n_in; (void)out_size;

    qmn_chunk_sum<<<BATCH * NCHUNK, 256>>>(x, emb);

    cudaLaunchConfig_t cfg = {};
    cfg.gridDim  = dim3(BATCH * NCHUNK, 1, 1);
    cfg.blockDim = dim3(256, 1, 1);
    cfg.dynamicSmemBytes = 0;
    cudaLaunchAttribute attr[1];
    attr[0].id = cudaLaunchAttributeProgrammaticStreamSerialization;
    attr[0].val.programmaticStreamSerializationAllowed = 1;
    cfg.attrs = attr;
    cfg.numAttrs = 1;
    cudaLaunchKernelEx(&cfg, qmn_states, x, emb, out);
}